// round 10
// baseline (speedup 1.0000x reference)
#include <cuda_runtime.h>
#include <cuda_bf16.h>
#include <cstdint>

// Problem constants
#define BSZ   128
#define CDIM  2048
#define HW    196          // 14*14
#define NDESC 32
#define NANS  1845
#define CD4   (CDIM / 4)   // 512 float4 per attended row

#define TSAMP 8            // samples per chunk: one W pass for count<=8
#define TA    3            // answers per warp (register budget)
#define APB   (8 * TA)     // 24 answers per block

typedef unsigned long long ull;

// Scratch (no allocations allowed)
__device__ float g_att[BSZ * CDIM];      // attended [B, C]
__device__ int   g_cnt[NDESC];           // samples per descriptor
__device__ int   g_list[NDESC * BSZ];    // sample ids per descriptor

// ---------------------------------------------------------------------------
// packed f32x2 helpers (ptxas never emits FFMA2 from C++ — PTX only)
// ---------------------------------------------------------------------------
__device__ __forceinline__ ull fma2(ull a, ull b, ull c) {
    ull r;
    asm("fma.rn.f32x2 %0, %1, %2, %3;" : "=l"(r) : "l"(a), "l"(b), "l"(c));
    return r;
}
__device__ __forceinline__ ull add2(ull a, ull b) {
    ull r;
    asm("add.rn.f32x2 %0, %1, %2;" : "=l"(r) : "l"(a), "l"(b));
    return r;
}

// ---------------------------------------------------------------------------
// Kernel A: attended[b,c] = (1/196) * sum_hw mask[b,hw] * feat[b,c,hw]
// grid (32, 128), block 256. Warp processes 4 channels/iter (8 LDG.128 in
// flight). Block (0,0) also builds the grouping tables.
// ---------------------------------------------------------------------------
__global__ void __launch_bounds__(256)
attend_kernel(const float* __restrict__ mask,
              const float* __restrict__ feat,
              const int* __restrict__ inst32) {
    __shared__ float4 smask[49];
    const int b   = blockIdx.y;
    const int tid = threadIdx.x;

    const float4* mrow = reinterpret_cast<const float4*>(mask + (size_t)b * HW);
    if (tid < 49) smask[tid] = mrow[tid];
    __syncthreads();

    const int warp = tid >> 5;
    const int lane = tid & 31;

    #pragma unroll
    for (int it = 0; it < 2; ++it) {
        const int c0 = blockIdx.x * 64 + it * 32 + warp * 4;   // 4-aligned
        const float4* fr[4];
        #pragma unroll
        for (int j = 0; j < 4; ++j)
            fr[j] = reinterpret_cast<const float4*>(
                        feat + ((size_t)b * CDIM + c0 + j) * HW);

        float4 fa[4], fb[4];
        #pragma unroll
        for (int j = 0; j < 4; ++j) fa[j] = fr[j][lane];
        if (lane < 17) {
            #pragma unroll
            for (int j = 0; j < 4; ++j) fb[j] = fr[j][lane + 32];
        }

        float s[4];
        float4 ma = smask[lane];
        #pragma unroll
        for (int j = 0; j < 4; ++j)
            s[j] = fa[j].x * ma.x + fa[j].y * ma.y + fa[j].z * ma.z + fa[j].w * ma.w;
        if (lane < 17) {
            float4 mb = smask[lane + 32];
            #pragma unroll
            for (int j = 0; j < 4; ++j)
                s[j] += fb[j].x * mb.x + fb[j].y * mb.y + fb[j].z * mb.z + fb[j].w * mb.w;
        }
        #pragma unroll
        for (int j = 0; j < 4; ++j)
            #pragma unroll
            for (int off = 16; off > 0; off >>= 1)
                s[j] += __shfl_xor_sync(0xffffffffu, s[j], off);

        if (lane == 0) {
            float4 o = make_float4(s[0] * (1.0f / HW), s[1] * (1.0f / HW),
                                   s[2] * (1.0f / HW), s[3] * (1.0f / HW));
            reinterpret_cast<float4*>(g_att)[((size_t)b * CDIM + c0) >> 2] = o;
        }
    }

    // ---- grouping tables, computed once by block (0,0) ----
    if (blockIdx.x == 0 && blockIdx.y == 0) {
        __shared__ int sh_inst[BSZ];
        __shared__ int sh_flag;
        if (tid == 0) sh_flag = 0;
        __syncthreads();
        if (tid < 64) {
            // int64 little-endian => odd 32-bit words of first 64 entries are 0
            if (inst32[2 * tid + 1] != 0) atomicOr(&sh_flag, 1);
        }
        __syncthreads();
        const bool is64 = (sh_flag == 0);
        if (tid < BSZ) sh_inst[tid] = is64 ? inst32[2 * tid] : inst32[tid];
        __syncthreads();
        if (tid == 0) {
            int cnt[NDESC];
            #pragma unroll
            for (int dd = 0; dd < NDESC; ++dd) cnt[dd] = 0;
            for (int bb = 0; bb < BSZ; ++bb) {
                int dd = sh_inst[bb];
                g_list[dd * BSZ + cnt[dd]++] = bb;
            }
            #pragma unroll
            for (int dd = 0; dd < NDESC; ++dd) g_cnt[dd] = cnt[dd];
        }
    }
}

// ---------------------------------------------------------------------------
// Kernel B: grouped GEMM — R8 shape (8 warps, 3 blocks/SM, TS=8 single W
// pass, __ldcs W stream batched 2 columns) + packed f32x2 math, TA=3.
// FMA2 issue at 5.2 TB/s: 1.13 instr/cyc/SM (under the 2/cyc pipe cap that
// limited R8's scalar TS=8 version to ~4.4 TB/s).
// preds[s,a] = sum_c att[s,c] * W[d,a,c] + bias[d,a].  grid (77, 32).
// ---------------------------------------------------------------------------
__global__ void __launch_bounds__(256, 3)
gemm_kernel(const float* __restrict__ Wm,
            const float* __restrict__ bias,
            float* __restrict__ out) {
    const int d     = blockIdx.y;
    const int count = g_cnt[d];
    if (count == 0) return;

    extern __shared__ float4 s_att[];      // [TSAMP][CD4] = 64 KB
    __shared__ int s_b[TSAMP];

    const int tid  = threadIdx.x;
    const int warp = tid >> 5;
    const int lane = tid & 31;

    const int aw = blockIdx.x * APB + warp * TA;   // first of TA answers
    const ulonglong2* __restrict__ W2 = reinterpret_cast<const ulonglong2*>(Wm);
    unsigned wrow[TA];
    #pragma unroll
    for (int ta = 0; ta < TA; ++ta) {
        int a = aw + ta; if (a >= NANS) a = NANS - 1;   // clamp; stores guarded
        wrow[ta] = (unsigned)((d * NANS + a) * CD4);
    }
    const float4* __restrict__ gatt4 = reinterpret_cast<const float4*>(g_att);
    const ulonglong2* __restrict__ A2 =
        reinterpret_cast<const ulonglong2*>(s_att);

    const int nchunks = (count + TSAMP - 1) / TSAMP;   // ==1 for ~98% of d

    for (int sc = 0; sc < nchunks; ++sc) {
        if (tid < TSAMP) {
            int si = sc * TSAMP + tid;
            s_b[tid] = (si < count) ? g_list[d * BSZ + si] : -1;
        }
        __syncthreads();
        // stage attended tile (full K), zeros for padding samples (L2 hits)
        for (int i = tid; i < TSAMP * CD4; i += 256) {
            int ts = i >> 9;            // / CD4
            int cc = i & (CD4 - 1);
            int bb = s_b[ts];
            float4 v = make_float4(0.f, 0.f, 0.f, 0.f);
            if (bb >= 0) v = gatt4[(size_t)bb * CD4 + cc];
            s_att[i] = v;
        }
        __syncthreads();

        ull acc[TA][TSAMP];
        #pragma unroll
        for (int ta = 0; ta < TA; ++ta)
            #pragma unroll
            for (int ts = 0; ts < TSAMP; ++ts) acc[ta][ts] = 0ull;

        // K loop: 512 float4 columns / 32 lanes = 16 iters, batched by 2
        #pragma unroll
        for (int it = 0; it < CD4 / 32; it += 2) {
            const int cc0 = it * 32 + lane;
            const int cc1 = cc0 + 32;
            ulonglong2 w[2][TA];
            #pragma unroll
            for (int ta = 0; ta < TA; ++ta) w[0][ta] = __ldcs(&W2[wrow[ta] + cc0]);
            #pragma unroll
            for (int ta = 0; ta < TA; ++ta) w[1][ta] = __ldcs(&W2[wrow[ta] + cc1]);

            #pragma unroll
            for (int h = 0; h < 2; ++h) {
                const int cc = it * 32 + h * 32 + lane;
                #pragma unroll
                for (int ts = 0; ts < TSAMP; ++ts) {
                    ulonglong2 av = A2[ts * CD4 + cc];
                    #pragma unroll
                    for (int ta = 0; ta < TA; ++ta) {
                        acc[ta][ts] = fma2(w[h][ta].x, av.x, acc[ta][ts]);
                        acc[ta][ts] = fma2(w[h][ta].y, av.y, acc[ta][ts]);
                    }
                }
            }
        }

        // butterfly reduce packed accs: every lane ends with full sums
        #pragma unroll
        for (int ta = 0; ta < TA; ++ta)
            #pragma unroll
            for (int ts = 0; ts < TSAMP; ++ts)
                #pragma unroll
                for (int off = 16; off > 0; off >>= 1)
                    acc[ta][ts] = add2(acc[ta][ts],
                        __shfl_xor_sync(0xffffffffu, acc[ta][ts], off));

        // lane l (<24) stores pair (ta = l/8, ts = l%8); lo+hi finishes K sum
        if (lane < TA * TSAMP) {
            int ta = lane >> 3;
            int ts = lane & 7;
            int a  = aw + ta;
            int bb = s_b[ts];
            if (a < NANS && bb >= 0) {
                ull v = acc[ta][ts];
                float lo = __uint_as_float((unsigned)(v & 0xffffffffull));
                float hi = __uint_as_float((unsigned)(v >> 32));
                out[(size_t)bb * NANS + a] = lo + hi + bias[(size_t)d * NANS + a];
            }
        }
        __syncthreads();   // protect s_b / s_att before next chunk rewrites
    }
}

// ---------------------------------------------------------------------------
extern "C" void kernel_launch(void* const* d_in, const int* in_sizes, int n_in,
                              void* d_out, int out_size) {
    const float* mask = (const float*)d_in[0];   // [B,1,14,14]
    const float* feat = (const float*)d_in[1];   // [B,C,14,14]
    const int*   inst = (const int*)d_in[2];     // [B] int64 or int32
    const float* Wm   = (const float*)d_in[3];   // [32,1845,2048]
    const float* bias = (const float*)d_in[4];   // [32,1845]
    float* out = (float*)d_out;                  // [B,1845]

    static const size_t GEMM_SMEM = TSAMP * CDIM * sizeof(float);   // 64 KB
    cudaFuncSetAttribute(gemm_kernel,
                         cudaFuncAttributeMaxDynamicSharedMemorySize,
                         (int)GEMM_SMEM);

    attend_kernel<<<dim3(32, 128), 256>>>(mask, feat, inst);
    gemm_kernel<<<dim3((NANS + APB - 1) / APB, NDESC), 256, GEMM_SMEM>>>(Wm, bias, out);
}

// round 11
// speedup vs baseline: 1.0023x; 1.0023x over previous
#include <cuda_runtime.h>
#include <cuda_bf16.h>
#include <cstdint>

// Problem constants
#define BSZ   128
#define CDIM  2048
#define HW    196          // 14*14
#define NDESC 32
#define NANS  1845
#define CD4   (CDIM / 4)   // 512 float4 per attended row

#define TSAMP 8            // samples per chunk: one W pass for count<=8
#define TA    4            // answers per warp
#define APB   (8 * TA)     // 32 answers per block

typedef unsigned long long ull;

// Scratch (no allocations allowed)
__device__ float g_att[BSZ * CDIM];      // attended [B, C]
__device__ int   g_cnt[NDESC];           // samples per descriptor
__device__ int   g_list[NDESC * BSZ];    // sample ids per descriptor

// ---------------------------------------------------------------------------
// packed f32x2 helpers (ptxas never emits FFMA2 from C++ — PTX only)
// ---------------------------------------------------------------------------
__device__ __forceinline__ ull fma2(ull a, ull b, ull c) {
    ull r;
    asm("fma.rn.f32x2 %0, %1, %2, %3;" : "=l"(r) : "l"(a), "l"(b), "l"(c));
    return r;
}
__device__ __forceinline__ ull add2(ull a, ull b) {
    ull r;
    asm("add.rn.f32x2 %0, %1, %2;" : "=l"(r) : "l"(a), "l"(b));
    return r;
}

// ---------------------------------------------------------------------------
// Kernel A: attended[b,c] = (1/196) * sum_hw mask[b,hw] * feat[b,c,hw]
// grid (32, 128), block 256. Warp processes 4 channels/iter (8 LDG.128 in
// flight). Block (0,0) also builds the grouping tables.
// ---------------------------------------------------------------------------
__global__ void __launch_bounds__(256)
attend_kernel(const float* __restrict__ mask,
              const float* __restrict__ feat,
              const int* __restrict__ inst32) {
    __shared__ float4 smask[49];
    const int b   = blockIdx.y;
    const int tid = threadIdx.x;

    const float4* mrow = reinterpret_cast<const float4*>(mask + (size_t)b * HW);
    if (tid < 49) smask[tid] = mrow[tid];
    __syncthreads();

    const int warp = tid >> 5;
    const int lane = tid & 31;

    #pragma unroll
    for (int it = 0; it < 2; ++it) {
        const int c0 = blockIdx.x * 64 + it * 32 + warp * 4;   // 4-aligned
        const float4* fr[4];
        #pragma unroll
        for (int j = 0; j < 4; ++j)
            fr[j] = reinterpret_cast<const float4*>(
                        feat + ((size_t)b * CDIM + c0 + j) * HW);

        float4 fa[4], fb[4];
        #pragma unroll
        for (int j = 0; j < 4; ++j) fa[j] = fr[j][lane];
        if (lane < 17) {
            #pragma unroll
            for (int j = 0; j < 4; ++j) fb[j] = fr[j][lane + 32];
        }

        float s[4];
        float4 ma = smask[lane];
        #pragma unroll
        for (int j = 0; j < 4; ++j)
            s[j] = fa[j].x * ma.x + fa[j].y * ma.y + fa[j].z * ma.z + fa[j].w * ma.w;
        if (lane < 17) {
            float4 mb = smask[lane + 32];
            #pragma unroll
            for (int j = 0; j < 4; ++j)
                s[j] += fb[j].x * mb.x + fb[j].y * mb.y + fb[j].z * mb.z + fb[j].w * mb.w;
        }
        #pragma unroll
        for (int j = 0; j < 4; ++j)
            #pragma unroll
            for (int off = 16; off > 0; off >>= 1)
                s[j] += __shfl_xor_sync(0xffffffffu, s[j], off);

        if (lane == 0) {
            float4 o = make_float4(s[0] * (1.0f / HW), s[1] * (1.0f / HW),
                                   s[2] * (1.0f / HW), s[3] * (1.0f / HW));
            reinterpret_cast<float4*>(g_att)[((size_t)b * CDIM + c0) >> 2] = o;
        }
    }

    // ---- grouping tables, computed once by block (0,0) ----
    if (blockIdx.x == 0 && blockIdx.y == 0) {
        __shared__ int sh_inst[BSZ];
        __shared__ int sh_flag;
        if (tid == 0) sh_flag = 0;
        __syncthreads();
        if (tid < 64) {
            // int64 little-endian => odd 32-bit words of first 64 entries are 0
            if (inst32[2 * tid + 1] != 0) atomicOr(&sh_flag, 1);
        }
        __syncthreads();
        const bool is64 = (sh_flag == 0);
        if (tid < BSZ) sh_inst[tid] = is64 ? inst32[2 * tid] : inst32[tid];
        __syncthreads();
        if (tid == 0) {
            int cnt[NDESC];
            #pragma unroll
            for (int dd = 0; dd < NDESC; ++dd) cnt[dd] = 0;
            for (int bb = 0; bb < BSZ; ++bb) {
                int dd = sh_inst[bb];
                g_list[dd * BSZ + cnt[dd]++] = bb;
            }
            #pragma unroll
            for (int dd = 0; dd < NDESC; ++dd) g_cnt[dd] = cnt[dd];
        }
    }
}

// ---------------------------------------------------------------------------
// Kernel B: grouped GEMM — half-warp sample split.
// 8 warps, 3 blocks/SM, TA=4, TS=8, one W pass, f32x2 math.
// Lanes 0-15 own samples 0-3; lanes 16-31 own samples 4-7. Each half covers
// the full K (32 columns per lane); the two halves issue identical W
// addresses, deduped by the L1 coalescer (no extra DRAM/L2 traffic).
// acc = 4x4 f32x2 = 32 regs -> fits the 3-blocks/SM register budget.
// preds[s,a] = sum_c att[s,c] * W[d,a,c] + bias[d,a].  grid (58, 32).
// ---------------------------------------------------------------------------
__global__ void __launch_bounds__(256, 3)
gemm_kernel(const float* __restrict__ Wm,
            const float* __restrict__ bias,
            float* __restrict__ out) {
    const int d     = blockIdx.y;
    const int count = g_cnt[d];
    if (count == 0) return;

    extern __shared__ float4 s_att[];      // [TSAMP][CD4] = 64 KB
    __shared__ int s_b[TSAMP];

    const int tid   = threadIdx.x;
    const int warp  = tid >> 5;
    const int lane  = tid & 31;
    const int hlane = lane & 15;           // lane within half-warp
    const int tsb   = (lane >> 4) * 4;     // sample base for this half (0 or 4)

    const int aw = blockIdx.x * APB + warp * TA;   // first of TA answers
    const ulonglong2* __restrict__ W2 = reinterpret_cast<const ulonglong2*>(Wm);
    unsigned wrow[TA];
    #pragma unroll
    for (int ta = 0; ta < TA; ++ta) {
        int a = aw + ta; if (a >= NANS) a = NANS - 1;   // clamp; stores guarded
        wrow[ta] = (unsigned)((d * NANS + a) * CD4);
    }
    const float4* __restrict__ gatt4 = reinterpret_cast<const float4*>(g_att);
    const ulonglong2* __restrict__ A2 =
        reinterpret_cast<const ulonglong2*>(s_att);

    const int nchunks = (count + TSAMP - 1) / TSAMP;   // ==1 for ~98% of d

    for (int sc = 0; sc < nchunks; ++sc) {
        if (tid < TSAMP) {
            int si = sc * TSAMP + tid;
            s_b[tid] = (si < count) ? g_list[d * BSZ + si] : -1;
        }
        __syncthreads();
        // stage attended tile (full K), zeros for padding samples (L2 hits)
        for (int i = tid; i < TSAMP * CD4; i += 256) {
            int ts = i >> 9;            // / CD4
            int cc = i & (CD4 - 1);
            int bb = s_b[ts];
            float4 v = make_float4(0.f, 0.f, 0.f, 0.f);
            if (bb >= 0) v = gatt4[(size_t)bb * CD4 + cc];
            s_att[i] = v;
        }
        __syncthreads();

        ull acc[TA][4];                 // 4 samples per half-warp
        #pragma unroll
        for (int ta = 0; ta < TA; ++ta)
            #pragma unroll
            for (int j = 0; j < 4; ++j) acc[ta][j] = 0ull;

        // K loop: each lane sweeps 32 columns (CD4 / 16), batched by 2.
        // Both halves issue the same W addresses (coalescer broadcast).
        #pragma unroll
        for (int it = 0; it < CD4 / 16; it += 2) {
            const int cc0 = it * 16 + hlane;
            const int cc1 = cc0 + 16;
            ulonglong2 w[2][TA];
            #pragma unroll
            for (int ta = 0; ta < TA; ++ta) w[0][ta] = __ldcs(&W2[wrow[ta] + cc0]);
            #pragma unroll
            for (int ta = 0; ta < TA; ++ta) w[1][ta] = __ldcs(&W2[wrow[ta] + cc1]);

            #pragma unroll
            for (int h = 0; h < 2; ++h) {
                const int cc = it * 16 + h * 16 + hlane;
                #pragma unroll
                for (int j = 0; j < 4; ++j) {
                    ulonglong2 av = A2[(tsb + j) * CD4 + cc];
                    #pragma unroll
                    for (int ta = 0; ta < TA; ++ta) {
                        acc[ta][j] = fma2(w[h][ta].x, av.x, acc[ta][j]);
                        acc[ta][j] = fma2(w[h][ta].y, av.y, acc[ta][j]);
                    }
                }
            }
        }

        // butterfly reduce within each half-warp (offsets 8..1)
        #pragma unroll
        for (int ta = 0; ta < TA; ++ta)
            #pragma unroll
            for (int j = 0; j < 4; ++j)
                #pragma unroll
                for (int off = 8; off > 0; off >>= 1)
                    acc[ta][j] = add2(acc[ta][j],
                        __shfl_xor_sync(0xffffffffu, acc[ta][j], off));

        // 32 lanes = 4 answers x 8 samples: half h, hlane = ta*4 + j
        {
            int ta = hlane >> 2;
            int j  = hlane & 3;
            int a  = aw + ta;
            int bb = s_b[tsb + j];
            if (a < NANS && bb >= 0) {
                ull v = acc[ta][j];
                float lo = __uint_as_float((unsigned)(v & 0xffffffffull));
                float hi = __uint_as_float((unsigned)(v >> 32));
                out[(size_t)bb * NANS + a] = lo + hi + bias[(size_t)d * NANS + a];
            }
        }
        __syncthreads();   // protect s_b / s_att before next chunk rewrites
    }
}

// ---------------------------------------------------------------------------
extern "C" void kernel_launch(void* const* d_in, const int* in_sizes, int n_in,
                              void* d_out, int out_size) {
    const float* mask = (const float*)d_in[0];   // [B,1,14,14]
    const float* feat = (const float*)d_in[1];   // [B,C,14,14]
    const int*   inst = (const int*)d_in[2];     // [B] int64 or int32
    const float* Wm   = (const float*)d_in[3];   // [32,1845,2048]
    const float* bias = (const float*)d_in[4];   // [32,1845]
    float* out = (float*)d_out;                  // [B,1845]

    static const size_t GEMM_SMEM = TSAMP * CDIM * sizeof(float);   // 64 KB
    cudaFuncSetAttribute(gemm_kernel,
                         cudaFuncAttributeMaxDynamicSharedMemorySize,
                         (int)GEMM_SMEM);

    attend_kernel<<<dim3(32, 128), 256>>>(mask, feat, inst);
    gemm_kernel<<<dim3((NANS + APB - 1) / APB, NDESC), 256, GEMM_SMEM>>>(Wm, bias, out);
}

// round 12
// speedup vs baseline: 1.1385x; 1.1359x over previous
#include <cuda_runtime.h>
#include <cuda_bf16.h>
#include <cstdint>

// Problem constants
#define BSZ   128
#define CDIM  2048
#define HW    196          // 14*14
#define NDESC 32
#define NANS  1845
#define CD4   (CDIM / 4)   // 512 float4 per attended row

#define TSAMP 4            // samples per chunk
#define TA    4            // answers per warp
#define APB   (8 * TA)     // 32 answers per block

// Scratch (no allocations allowed)
__device__ float g_att[BSZ * CDIM];      // attended [B, C]
__device__ int   g_cnt[NDESC];           // samples per descriptor
__device__ int   g_list[NDESC * BSZ];    // sample ids per descriptor

// ---------------------------------------------------------------------------
// Kernel A: attended[b,c] = (1/196) * sum_hw mask[b,hw] * feat[b,c,hw]
// grid (32, 128), block 256. Warp processes 4 channels/iter (8 LDG.128 in
// flight). Block (0,0) also builds the grouping tables.
// ---------------------------------------------------------------------------
__global__ void __launch_bounds__(256)
attend_kernel(const float* __restrict__ mask,
              const float* __restrict__ feat,
              const int* __restrict__ inst32) {
    __shared__ float4 smask[49];
    const int b   = blockIdx.y;
    const int tid = threadIdx.x;

    const float4* mrow = reinterpret_cast<const float4*>(mask + (size_t)b * HW);
    if (tid < 49) smask[tid] = mrow[tid];
    __syncthreads();

    const int warp = tid >> 5;
    const int lane = tid & 31;

    #pragma unroll
    for (int it = 0; it < 2; ++it) {
        const int c0 = blockIdx.x * 64 + it * 32 + warp * 4;   // 4-aligned
        const float4* fr[4];
        #pragma unroll
        for (int j = 0; j < 4; ++j)
            fr[j] = reinterpret_cast<const float4*>(
                        feat + ((size_t)b * CDIM + c0 + j) * HW);

        float4 fa[4], fb[4];
        #pragma unroll
        for (int j = 0; j < 4; ++j) fa[j] = fr[j][lane];
        if (lane < 17) {
            #pragma unroll
            for (int j = 0; j < 4; ++j) fb[j] = fr[j][lane + 32];
        }

        float s[4];
        float4 ma = smask[lane];
        #pragma unroll
        for (int j = 0; j < 4; ++j)
            s[j] = fa[j].x * ma.x + fa[j].y * ma.y + fa[j].z * ma.z + fa[j].w * ma.w;
        if (lane < 17) {
            float4 mb = smask[lane + 32];
            #pragma unroll
            for (int j = 0; j < 4; ++j)
                s[j] += fb[j].x * mb.x + fb[j].y * mb.y + fb[j].z * mb.z + fb[j].w * mb.w;
        }
        #pragma unroll
        for (int j = 0; j < 4; ++j)
            #pragma unroll
            for (int off = 16; off > 0; off >>= 1)
                s[j] += __shfl_xor_sync(0xffffffffu, s[j], off);

        if (lane == 0) {
            float4 o = make_float4(s[0] * (1.0f / HW), s[1] * (1.0f / HW),
                                   s[2] * (1.0f / HW), s[3] * (1.0f / HW));
            reinterpret_cast<float4*>(g_att)[((size_t)b * CDIM + c0) >> 2] = o;
        }
    }

    // ---- grouping tables, computed once by block (0,0) ----
    if (blockIdx.x == 0 && blockIdx.y == 0) {
        __shared__ int sh_inst[BSZ];
        __shared__ int sh_flag;
        if (tid == 0) sh_flag = 0;
        __syncthreads();
        if (tid < 64) {
            // int64 little-endian => odd 32-bit words of first 64 entries are 0
            if (inst32[2 * tid + 1] != 0) atomicOr(&sh_flag, 1);
        }
        __syncthreads();
        const bool is64 = (sh_flag == 0);
        if (tid < BSZ) sh_inst[tid] = is64 ? inst32[2 * tid] : inst32[tid];
        __syncthreads();
        if (tid == 0) {
            int cnt[NDESC];
            #pragma unroll
            for (int dd = 0; dd < NDESC; ++dd) cnt[dd] = 0;
            for (int bb = 0; bb < BSZ; ++bb) {
                int dd = sh_inst[bb];
                g_list[dd * BSZ + cnt[dd]++] = bb;
            }
            #pragma unroll
            for (int dd = 0; dd < NDESC; ++dd) g_cnt[dd] = cnt[dd];
        }
    }
}

// ---------------------------------------------------------------------------
// Kernel B: grouped GEMM — R3 shape at 4 blocks/SM (32 warps), batch-1
// W register stream. TS=4, TA=4, scalar FFMA.
// Short 64-FFMA compute phases => warps re-enter load-issue 2x faster than
// batch-2; 32 warps x 2KB outstanding covers DRAM latency.
// preds[s,a] = sum_c att[s,c] * W[d,a,c] + bias[d,a].  grid (58, 32).
// ---------------------------------------------------------------------------
__global__ void __launch_bounds__(256, 4)
gemm_kernel(const float* __restrict__ Wm,
            const float* __restrict__ bias,
            float* __restrict__ out) {
    const int d     = blockIdx.y;
    const int count = g_cnt[d];
    if (count == 0) return;

    extern __shared__ float4 s_att[];      // [TSAMP][CD4] = 32 KB
    __shared__ int s_b[TSAMP];

    const int tid  = threadIdx.x;
    const int warp = tid >> 5;
    const int lane = tid & 31;

    const int aw = blockIdx.x * APB + warp * TA;   // first of TA answers
    const float4* __restrict__ W4 = reinterpret_cast<const float4*>(Wm);
    unsigned wrow[TA];
    #pragma unroll
    for (int ta = 0; ta < TA; ++ta) {
        int a = aw + ta; if (a >= NANS) a = NANS - 1;   // clamp; stores guarded
        wrow[ta] = (unsigned)((d * NANS + a) * CD4);
    }
    const float4* __restrict__ gatt4 = reinterpret_cast<const float4*>(g_att);

    const int nchunks = (count + TSAMP - 1) / TSAMP;

    for (int sc = 0; sc < nchunks; ++sc) {
        if (tid < TSAMP) {
            int si = sc * TSAMP + tid;
            s_b[tid] = (si < count) ? g_list[d * BSZ + si] : -1;
        }
        __syncthreads();
        // stage attended tile (full K), zeros for padding samples (L2 hits)
        for (int i = tid; i < TSAMP * CD4; i += 256) {
            int ts = i >> 9;            // / CD4
            int cc = i & (CD4 - 1);
            int bb = s_b[ts];
            float4 v = make_float4(0.f, 0.f, 0.f, 0.f);
            if (bb >= 0) v = gatt4[(size_t)bb * CD4 + cc];
            s_att[i] = v;
        }
        __syncthreads();

        float acc[TA][TSAMP];
        #pragma unroll
        for (int ta = 0; ta < TA; ++ta)
            #pragma unroll
            for (int ts = 0; ts < TSAMP; ++ts) acc[ta][ts] = 0.0f;

        // K loop: 512 float4 columns / 32 lanes = 16 iters, batch-1:
        // 4 independent LDG.128 then 64 FFMA — short compute phase.
        #pragma unroll
        for (int it = 0; it < CD4 / 32; ++it) {
            const int cc = it * 32 + lane;
            float4 w[TA];
            #pragma unroll
            for (int ta = 0; ta < TA; ++ta) w[ta] = W4[wrow[ta] + cc];

            #pragma unroll
            for (int ts = 0; ts < TSAMP; ++ts) {
                float4 av = s_att[ts * CD4 + cc];
                #pragma unroll
                for (int ta = 0; ta < TA; ++ta) {
                    acc[ta][ts] += w[ta].x * av.x;
                    acc[ta][ts] += w[ta].y * av.y;
                    acc[ta][ts] += w[ta].z * av.z;
                    acc[ta][ts] += w[ta].w * av.w;
                }
            }
        }

        // butterfly reduce: every lane ends with full sums
        #pragma unroll
        for (int ta = 0; ta < TA; ++ta)
            #pragma unroll
            for (int ts = 0; ts < TSAMP; ++ts)
                #pragma unroll
                for (int off = 16; off > 0; off >>= 1)
                    acc[ta][ts] += __shfl_xor_sync(0xffffffffu, acc[ta][ts], off);

        // lane l (<16) stores pair (ta = l/4, ts = l%4)
        if (lane < 16) {
            int ta = lane >> 2;
            int ts = lane & 3;
            int a  = aw + ta;
            int bb = s_b[ts];
            if (a < NANS && bb >= 0)
                out[(size_t)bb * NANS + a] = acc[ta][ts] + bias[(size_t)d * NANS + a];
        }
        __syncthreads();   // protect s_b / s_att before next chunk rewrites
    }
}

// ---------------------------------------------------------------------------
extern "C" void kernel_launch(void* const* d_in, const int* in_sizes, int n_in,
                              void* d_out, int out_size) {
    const float* mask = (const float*)d_in[0];   // [B,1,14,14]
    const float* feat = (const float*)d_in[1];   // [B,C,14,14]
    const int*   inst = (const int*)d_in[2];     // [B] int64 or int32
    const float* Wm   = (const float*)d_in[3];   // [32,1845,2048]
    const float* bias = (const float*)d_in[4];   // [32,1845]
    float* out = (float*)d_out;                  // [B,1845]

    static const size_t GEMM_SMEM = TSAMP * CDIM * sizeof(float);   // 32 KB
    cudaFuncSetAttribute(gemm_kernel,
                         cudaFuncAttributeMaxDynamicSharedMemorySize,
                         (int)GEMM_SMEM);

    attend_kernel<<<dim3(32, 128), 256>>>(mask, feat, inst);
    gemm_kernel<<<dim3((NANS + APB - 1) / APB, NDESC), 256, GEMM_SMEM>>>(Wm, bias, out);
}

// round 13
// speedup vs baseline: 1.1557x; 1.0152x over previous
#include <cuda_runtime.h>
#include <cuda_bf16.h>
#include <cstdint>

// Problem constants
#define BSZ   128
#define CDIM  2048
#define HW    196          // 14*14
#define NDESC 32
#define NANS  1845
#define CD4   (CDIM / 4)   // 512 float4 per attended row

#define TSAMP 8            // samples per chunk: one W DRAM pass for count<=8
#define TA    4            // answers per warp
#define APB   32           // answers per block (8 answer-warps x 4)

// Scratch (no allocations allowed)
__device__ float g_att[BSZ * CDIM];      // attended [B, C]
__device__ int   g_cnt[NDESC];           // samples per descriptor
__device__ int   g_list[NDESC * BSZ];    // sample ids per descriptor

// ---------------------------------------------------------------------------
// Kernel A: attended[b,c] = (1/196) * sum_hw mask[b,hw] * feat[b,c,hw]
// grid (32, 128), block 256. Warp processes 4 channels/iter (8 LDG.128 in
// flight). Block (0,0) also builds the grouping tables.
// ---------------------------------------------------------------------------
__global__ void __launch_bounds__(256)
attend_kernel(const float* __restrict__ mask,
              const float* __restrict__ feat,
              const int* __restrict__ inst32) {
    __shared__ float4 smask[49];
    const int b   = blockIdx.y;
    const int tid = threadIdx.x;

    const float4* mrow = reinterpret_cast<const float4*>(mask + (size_t)b * HW);
    if (tid < 49) smask[tid] = mrow[tid];
    __syncthreads();

    const int warp = tid >> 5;
    const int lane = tid & 31;

    #pragma unroll
    for (int it = 0; it < 2; ++it) {
        const int c0 = blockIdx.x * 64 + it * 32 + warp * 4;   // 4-aligned
        const float4* fr[4];
        #pragma unroll
        for (int j = 0; j < 4; ++j)
            fr[j] = reinterpret_cast<const float4*>(
                        feat + ((size_t)b * CDIM + c0 + j) * HW);

        float4 fa[4], fb[4];
        #pragma unroll
        for (int j = 0; j < 4; ++j) fa[j] = fr[j][lane];
        if (lane < 17) {
            #pragma unroll
            for (int j = 0; j < 4; ++j) fb[j] = fr[j][lane + 32];
        }

        float s[4];
        float4 ma = smask[lane];
        #pragma unroll
        for (int j = 0; j < 4; ++j)
            s[j] = fa[j].x * ma.x + fa[j].y * ma.y + fa[j].z * ma.z + fa[j].w * ma.w;
        if (lane < 17) {
            float4 mb = smask[lane + 32];
            #pragma unroll
            for (int j = 0; j < 4; ++j)
                s[j] += fb[j].x * mb.x + fb[j].y * mb.y + fb[j].z * mb.z + fb[j].w * mb.w;
        }
        #pragma unroll
        for (int j = 0; j < 4; ++j)
            #pragma unroll
            for (int off = 16; off > 0; off >>= 1)
                s[j] += __shfl_xor_sync(0xffffffffu, s[j], off);

        if (lane == 0) {
            float4 o = make_float4(s[0] * (1.0f / HW), s[1] * (1.0f / HW),
                                   s[2] * (1.0f / HW), s[3] * (1.0f / HW));
            reinterpret_cast<float4*>(g_att)[((size_t)b * CDIM + c0) >> 2] = o;
        }
    }

    // ---- grouping tables, computed once by block (0,0) ----
    if (blockIdx.x == 0 && blockIdx.y == 0) {
        __shared__ int sh_inst[BSZ];
        __shared__ int sh_flag;
        if (tid == 0) sh_flag = 0;
        __syncthreads();
        if (tid < 64) {
            // int64 little-endian => odd 32-bit words of first 64 entries are 0
            if (inst32[2 * tid + 1] != 0) atomicOr(&sh_flag, 1);
        }
        __syncthreads();
        const bool is64 = (sh_flag == 0);
        if (tid < BSZ) sh_inst[tid] = is64 ? inst32[2 * tid] : inst32[tid];
        __syncthreads();
        if (tid == 0) {
            int cnt[NDESC];
            #pragma unroll
            for (int dd = 0; dd < NDESC; ++dd) cnt[dd] = 0;
            for (int bb = 0; bb < BSZ; ++bb) {
                int dd = sh_inst[bb];
                g_list[dd * BSZ + cnt[dd]++] = bb;
            }
            #pragma unroll
            for (int dd = 0; dd < NDESC; ++dd) g_cnt[dd] = cnt[dd];
        }
    }
}

// ---------------------------------------------------------------------------
// Kernel B: grouped GEMM — twin-warp W sharing.
// 512 threads = 16 warps: warps 0-7 handle samples 0-3, warps 8-15 handle
// samples 4-7 for the SAME 32 answers. Each warp keeps the R12 profile
// (TS=4 scalar, batch-1, 64 regs) while the warp pair covers TS=8 in a
// single W DRAM pass: the twin's identical LDG addresses hit L2.
// Warps whose sample-half is all padding skip the K loop (halves L2 reads
// for count<=4 descriptors).
// preds[s,a] = sum_c att[s,c] * W[d,a,c] + bias[d,a].  grid (58, 32).
// ---------------------------------------------------------------------------
__global__ void __launch_bounds__(512, 2)
gemm_kernel(const float* __restrict__ Wm,
            const float* __restrict__ bias,
            float* __restrict__ out) {
    const int d     = blockIdx.y;
    const int count = g_cnt[d];
    if (count == 0) return;

    extern __shared__ float4 s_att[];      // [TSAMP][CD4] = 64 KB
    __shared__ int s_b[TSAMP];

    const int tid   = threadIdx.x;
    const int warp  = tid >> 5;
    const int lane  = tid & 31;
    const int awarp = warp & 7;            // answer-warp id (0..7)
    const int tsb   = (warp >> 3) * 4;     // sample base: 0 or 4

    const int aw = blockIdx.x * APB + awarp * TA;  // first of TA answers
    const float4* __restrict__ W4 = reinterpret_cast<const float4*>(Wm);
    unsigned wrow[TA];
    #pragma unroll
    for (int ta = 0; ta < TA; ++ta) {
        int a = aw + ta; if (a >= NANS) a = NANS - 1;   // clamp; stores guarded
        wrow[ta] = (unsigned)((d * NANS + a) * CD4);
    }
    const float4* __restrict__ gatt4 = reinterpret_cast<const float4*>(g_att);

    const int nchunks = (count + TSAMP - 1) / TSAMP;   // ==1 for ~98% of d

    for (int sc = 0; sc < nchunks; ++sc) {
        if (tid < TSAMP) {
            int si = sc * TSAMP + tid;
            s_b[tid] = (si < count) ? g_list[d * BSZ + si] : -1;
        }
        __syncthreads();
        // stage attended tile (full K), zeros for padding samples (L2 hits)
        #pragma unroll
        for (int r = 0; r < TSAMP; ++r) {          // 4096 float4 / 512 thr
            int i  = r * 512 + tid;
            int ts = i >> 9;            // / CD4
            int cc = i & (CD4 - 1);
            int bb = s_b[ts];
            float4 v = make_float4(0.f, 0.f, 0.f, 0.f);
            if (bb >= 0) v = gatt4[(size_t)bb * CD4 + cc];
            s_att[i] = v;
        }
        __syncthreads();

        // whole warp skips if its 4 samples are all padding
        if (s_b[tsb] >= 0) {
            float acc[TA][4];
            #pragma unroll
            for (int ta = 0; ta < TA; ++ta)
                #pragma unroll
                for (int j = 0; j < 4; ++j) acc[ta][j] = 0.0f;

            // K loop: 512 float4 columns / 32 lanes = 16 iters, batch-1
            #pragma unroll
            for (int it = 0; it < CD4 / 32; ++it) {
                const int cc = it * 32 + lane;
                float4 w[TA];
                #pragma unroll
                for (int ta = 0; ta < TA; ++ta) w[ta] = W4[wrow[ta] + cc];

                #pragma unroll
                for (int j = 0; j < 4; ++j) {
                    float4 av = s_att[(tsb + j) * CD4 + cc];
                    #pragma unroll
                    for (int ta = 0; ta < TA; ++ta) {
                        acc[ta][j] += w[ta].x * av.x;
                        acc[ta][j] += w[ta].y * av.y;
                        acc[ta][j] += w[ta].z * av.z;
                        acc[ta][j] += w[ta].w * av.w;
                    }
                }
            }

            // butterfly reduce: every lane ends with full sums
            #pragma unroll
            for (int ta = 0; ta < TA; ++ta)
                #pragma unroll
                for (int j = 0; j < 4; ++j)
                    #pragma unroll
                    for (int off = 16; off > 0; off >>= 1)
                        acc[ta][j] += __shfl_xor_sync(0xffffffffu, acc[ta][j], off);

            // lane l (<16) stores pair (ta = l/4, j = l%4)
            if (lane < 16) {
                int ta = lane >> 2;
                int j  = lane & 3;
                int a  = aw + ta;
                int bb = s_b[tsb + j];
                if (a < NANS && bb >= 0)
                    out[(size_t)bb * NANS + a] =
                        acc[ta][j] + bias[(size_t)d * NANS + a];
            }
        }
        __syncthreads();   // protect s_b / s_att before next chunk rewrites
    }
}

// ---------------------------------------------------------------------------
extern "C" void kernel_launch(void* const* d_in, const int* in_sizes, int n_in,
                              void* d_out, int out_size) {
    const float* mask = (const float*)d_in[0];   // [B,1,14,14]
    const float* feat = (const float*)d_in[1];   // [B,C,14,14]
    const int*   inst = (const int*)d_in[2];     // [B] int64 or int32
    const float* Wm   = (const float*)d_in[3];   // [32,1845,2048]
    const float* bias = (const float*)d_in[4];   // [32,1845]
    float* out = (float*)d_out;                  // [B,1845]

    static const size_t GEMM_SMEM = TSAMP * CDIM * sizeof(float);   // 64 KB
    cudaFuncSetAttribute(gemm_kernel,
                         cudaFuncAttributeMaxDynamicSharedMemorySize,
                         (int)GEMM_SMEM);

    attend_kernel<<<dim3(32, 128), 256>>>(mask, feat, inst);
    gemm_kernel<<<dim3((NANS + APB - 1) / APB, NDESC), 512, GEMM_SMEM>>>(Wm, bias, out);
}